// round 9
// baseline (speedup 1.0000x reference)
#include <cuda_runtime.h>
#include <cstdint>
#include <cstddef>

// CTRNN persistent kernel, round 9: depth-2 W lookahead via SHIFT REGISTER
// (fixes R8's odd-chunk-count parity bug: buffers are shifted each
//  iteration instead of indexed by c&1, so the cross-step invariant
//  "wa=chunk0, wb=chunk1" holds for any CHUNKS_PER_G).
// T=512, B=256, I=64, H=256. 128 CTAs x 512 threads, 2 batches/CTA.
//
// 4 k-groups of 128 threads; group g owns augmented rows [80g, 80g+80)
// in a PRIVATE smem slice; serves outputs j0 = tid&127, j1 = j0+128.
// Per group: 52 W rows via smem (13 chunks), 28 register-resident (14 u64/j).
// Chunk c consumes wa while issuing the LDS for chunk (c+2)%13 into wb;
// c=11,12 fetch NEXT step's chunks 0,1 BEFORE the CTA barrier (W smem is
// constant after init -> hoist safe). Keeps the LDS pipe fed across the
// exchange/finalize gap.

#define T_STEPS 512
#define BATCH   256
#define IN_SZ   64
#define HID     256
#define NTHR    512
#define NCTA    (BATCH / 2)

#define NGROUP        4
#define ROWS_PER_G    80
#define CHUNKS_PER_G  13          // 52 smem W rows per group
#define SMEM_ROWS_G   52
#define RF_U64        14          // 28 reg W rows per group (per j)
#define TOTAL_CHUNKS  (NGROUP * CHUNKS_PER_G)   // 52

typedef unsigned long long u64;

#define SMEM_W_BYTES   (TOTAL_CHUNKS * HID * 16)     // 212992
#define HAUG_STRIDE    88                            // 80 rows + pad (16B mult)
#define HAUG_OFF       SMEM_W_BYTES
#define RED_OFF        (HAUG_OFF + NGROUP * 2 * HAUG_STRIDE * 4)   // +2816
#define RED_PAR_FLOATS (2 * NGROUP * HID)            // 2048 per parity
#define SMEM_TOTAL     (RED_OFF + 2 * RED_PAR_FLOATS * 4)          // 232192

__device__ __forceinline__ u64 fma2(u64 a, u64 b, u64 c) {
    u64 d;
    asm("fma.rn.f32x2 %0, %1, %2, %3;" : "=l"(d) : "l"(a), "l"(b), "l"(c));
    return d;
}
__device__ __forceinline__ float sum2(u64 a) {
    float lo, hi;
    asm("mov.b64 {%0, %1}, %2;" : "=f"(lo), "=f"(hi) : "l"(a));
    return lo + hi;
}
__device__ __forceinline__ const float* wrow(const float* Win, const float* Whh,
                                             int j, int aug) {
    return (aug < IN_SZ) ? &Win[j * IN_SZ + aug] : &Whh[j * HID + (aug - IN_SZ)];
}

__global__ void __launch_bounds__(NTHR, 1)
ctrnn_wpipe2s_kernel(const float* __restrict__ x,
                     const float* __restrict__ h0,
                     const float* __restrict__ noise,
                     const float* __restrict__ Win,
                     const float* __restrict__ bin,
                     const float* __restrict__ Whh,
                     const float* __restrict__ bhh,
                     float* __restrict__ out,
                     float* __restrict__ hlast)
{
    extern __shared__ unsigned char smem_raw[];
    ulonglong2* Wsm = reinterpret_cast<ulonglong2*>(smem_raw);
    float* haug = reinterpret_cast<float*>(smem_raw + HAUG_OFF);  // [4][2][88]
    float* red  = reinterpret_cast<float*>(smem_raw + RED_OFF);   // [2][2][4][256]

    const int tid = threadIdx.x;
    const int g   = tid >> 7;          // k-group 0..3
    const int jl  = tid & 127;
    const int j0  = jl;
    const int j1  = jl + 128;
    const int b0  = blockIdx.x * 2;
    const int b1  = b0 + 1;

    // ---- stage W smem: chunk i covers aug rows 80g+4i..+3, cols j0 and j1 ----
    for (int i = 0; i < CHUNKS_PER_G; ++i) {
        const int aug = ROWS_PER_G * g + 4 * i;
        *reinterpret_cast<float4*>(&Wsm[(g * CHUNKS_PER_G + i) * HID + j0]) =
            *reinterpret_cast<const float4*>(wrow(Win, Whh, j0, aug));
        *reinterpret_cast<float4*>(&Wsm[(g * CHUNKS_PER_G + i) * HID + j1]) =
            *reinterpret_cast<const float4*>(wrow(Win, Whh, j1, aug));
    }

    // ---- register W rows: aug 80g+52 .. 80g+79 (28 rows = 14 u64 per j) ----
    u64 wr0[RF_U64], wr1[RF_U64];
    #pragma unroll
    for (int m = 0; m < RF_U64; ++m) {
        const int aug = ROWS_PER_G * g + SMEM_ROWS_G + 2 * m;
        wr0[m] = *reinterpret_cast<const u64*>(wrow(Win, Whh, j0, aug));
        wr1[m] = *reinterpret_cast<const u64*>(wrow(Win, Whh, j1, aug));
    }

    // ---- finalize identity ----
    const int  nrows = (g == 0) ? 16 : 80;
    const bool act   = jl < nrows;
    const int  myj   = (g == 0) ? jl : ((g == 1 ? 16 : (g == 2 ? 96 : 176)) + jl);
    const int  lidx  = (g == 0) ? 64 + jl : jl;   // index within own slice
    const float bsum = act ? (bin[myj] + bhh[myj]) : 0.f;

    // x staging identity (group 0 only)
    const int xb = jl >> 6;
    const int xi = jl & 63;
    const int xbatch = xb ? b1 : b0;

    float* myA = haug + (g * 2 + 0) * HAUG_STRIDE;
    float* myB = haug + (g * 2 + 1) * HAUG_STRIDE;

    // ---- initial staging of own slice ----
    if (act) {
        myA[lidx] = h0[b0 * HID + myj];
        myB[lidx] = h0[b1 * HID + myj];
    }
    if (g == 0)
        (xb ? myB : myA)[xi] = x[(size_t)xbatch * IN_SZ + xi];
    float nz = act ? (noise[myj] + bsum) : 0.f;
    __syncthreads();

    const ulonglong2* wp0 = Wsm + (size_t)(g * CHUNKS_PER_G) * HID + j0;
    const ulonglong2* wp1 = Wsm + (size_t)(g * CHUNKS_PER_G) * HID + j1;

    // ---- prime the shift-register lookahead: wa=chunk0, wb=chunk1 ----
    ulonglong2 wa0 = wp0[0],   wa1 = wp1[0];
    ulonglong2 wb0 = wp0[HID], wb1 = wp1[HID];

    for (int t = 0; t < T_STEPS; ++t) {
        float* redp = red + (t & 1) * RED_PAR_FLOATS;

        // prefetch next x / noise
        const int tn = (t + 1 < T_STEPS) ? t + 1 : t;
        float xn = 0.f, nzn = 0.f;
        if (g == 0) xn = x[((size_t)tn * BATCH + xbatch) * IN_SZ + xi];
        if (act)    nzn = noise[(size_t)tn * HID + myj] + bsum;

        // ---- FMA phase: 4 accumulator chains (batch x j) ----
        u64 aA0 = 0, aA1 = 0, aB0 = 0, aB1 = 0;

        #pragma unroll
        for (int c = 0; c < CHUNKS_PER_G; ++c) {
            // consume head of the shift register
            const ulonglong2 w0 = wa0;
            const ulonglong2 w1 = wa1;
            // shift: wb -> wa, then load chunk (c+2)%13 into wb.
            // c=11 loads next-step chunk 0, c=12 next-step chunk 1; loop
            // exit invariant: wa=chunk0, wb=chunk1 (any chunk count).
            wa0 = wb0;  wa1 = wb1;
            int nc = c + 2;
            if (nc >= CHUNKS_PER_G) nc -= CHUNKS_PER_G;
            wb0 = wp0[(size_t)nc * HID];
            wb1 = wp1[(size_t)nc * HID];

            ulonglong2 ha = *reinterpret_cast<const ulonglong2*>(&myA[4 * c]);
            ulonglong2 hb = *reinterpret_cast<const ulonglong2*>(&myB[4 * c]);
            aA0 = fma2(w0.x, ha.x, aA0);  aA0 = fma2(w0.y, ha.y, aA0);
            aA1 = fma2(w1.x, ha.x, aA1);  aA1 = fma2(w1.y, ha.y, aA1);
            aB0 = fma2(w0.x, hb.x, aB0);  aB0 = fma2(w0.y, hb.y, aB0);
            aB1 = fma2(w1.x, hb.x, aB1);  aB1 = fma2(w1.y, hb.y, aB1);
        }
        // register W rows: 7 pairs cover rows +52..+79
        #pragma unroll
        for (int i = 0; i < RF_U64 / 2; ++i) {
            ulonglong2 ha = *reinterpret_cast<const ulonglong2*>(&myA[SMEM_ROWS_G + 4 * i]);
            ulonglong2 hb = *reinterpret_cast<const ulonglong2*>(&myB[SMEM_ROWS_G + 4 * i]);
            aA0 = fma2(wr0[2 * i], ha.x, aA0);  aA0 = fma2(wr0[2 * i + 1], ha.y, aA0);
            aA1 = fma2(wr1[2 * i], ha.x, aA1);  aA1 = fma2(wr1[2 * i + 1], ha.y, aA1);
            aB0 = fma2(wr0[2 * i], hb.x, aB0);  aB0 = fma2(wr0[2 * i + 1], hb.y, aB0);
            aB1 = fma2(wr1[2 * i], hb.x, aB1);  aB1 = fma2(wr1[2 * i + 1], hb.y, aB1);
        }

        redp[(0 * NGROUP + g) * HID + j0] = sum2(aA0);
        redp[(0 * NGROUP + g) * HID + j1] = sum2(aA1);
        redp[(1 * NGROUP + g) * HID + j0] = sum2(aB0);
        redp[(1 * NGROUP + g) * HID + j1] = sum2(aB1);
        __syncthreads();                       // the ONE full-CTA barrier

        // ---- finalize own j-range ----
        if (act) {
            const float* rA = redp;
            const float* rB = redp + NGROUP * HID;
            const float sA = rA[0 * HID + myj] + rA[1 * HID + myj]
                           + rA[2 * HID + myj] + rA[3 * HID + myj];
            const float sB = rB[0 * HID + myj] + rB[1 * HID + myj]
                           + rB[2 * HID + myj] + rB[3 * HID + myj];
            const float hnA = fmaxf(myA[lidx] * 0.8f + (sA + nz) * 0.2f, 0.f);
            const float hnB = fmaxf(myB[lidx] * 0.8f + (sB + nz) * 0.2f, 0.f);
            if (out) {
                out[((size_t)t * BATCH + b0) * HID + myj] = hnA;
                out[((size_t)t * BATCH + b1) * HID + myj] = hnB;
            }
            myA[lidx] = hnA;
            myB[lidx] = hnB;
        }
        if (g == 0)
            (xb ? myB : myA)[xi] = xn;
        nz = nzn;

        asm volatile("bar.sync %0, %1;" :: "r"(g + 1), "r"(128) : "memory");
    }

    if (hlast && act) {
        hlast[b0 * HID + myj] = myA[lidx];
        hlast[b1 * HID + myj] = myB[lidx];
    }
}

extern "C" void kernel_launch(void* const* d_in, const int* in_sizes, int n_in,
                              void* d_out, int out_size)
{
    const float* x     = (const float*)d_in[0];   // [512,256,64]
    const float* h0    = (const float*)d_in[1];   // [256,256]
    const float* noise = (const float*)d_in[2];   // [512,256]
    const float* Win   = (const float*)d_in[3];   // [256,64]
    const float* bin   = (const float*)d_in[4];   // [256]
    const float* Whh   = (const float*)d_in[5];   // [256,256]
    const float* bhh   = (const float*)d_in[6];   // [256]

    const size_t TBH = (size_t)T_STEPS * BATCH * HID;
    const size_t BH  = (size_t)BATCH * HID;

    float* out   = nullptr;
    float* hlast = nullptr;
    if ((size_t)out_size >= TBH) {
        out = (float*)d_out;
        if ((size_t)out_size >= TBH + BH) hlast = (float*)d_out + TBH;
    } else {
        hlast = (float*)d_out;
    }

    static bool attr_set = false;
    if (!attr_set) {
        cudaFuncSetAttribute(ctrnn_wpipe2s_kernel,
                             cudaFuncAttributeMaxDynamicSharedMemorySize, SMEM_TOTAL);
        attr_set = true;
    }

    ctrnn_wpipe2s_kernel<<<NCTA, NTHR, SMEM_TOTAL>>>(
        x, h0, noise, Win, bin, Whh, bhh, out, hlast);
}

// round 10
// speedup vs baseline: 1.0575x; 1.0575x over previous
#include <cuda_runtime.h>
#include <cstdint>
#include <cstddef>

// CTRNN persistent kernel, round 10: R7 chassis + INTERLEAVED chunk/RF
// schedule. T=512, B=256, I=64, H=256. 128 CTAs x 512 threads, 2 batches/CTA.
//
// 4 k-groups of 128 threads; group g owns augmented rows [80g, 80g+80)
// in a PRIVATE smem slice; serves outputs j0 = tid&127, j1 = j0+128.
// Per group: 48 W rows via smem (12 chunks), 32 register-resident (16 u64/j).
//
// R10 change: the 12 smem-chunk iterations (LDS-heavy: 10 wf vs 8 FMA2) and
// 8 RF iterations (FMA-heavy: 2 wf vs 8 FMA2) are interleaved in a 3:2
// pattern (r c c r c, x4) instead of run as two phases. Since per-step
// barriers resync all 16 warps, the phased version idles the FMA pipe in the
// chunk phase and the LDS pipe in the RF phase; interleaving flattens both.
// W lookahead stays depth-1 (R7): each chunk slot consumes the buffered W
// and issues the next chunk's LDS; the last chunk slot fetches NEXT step's
// chunk 0 before the barrier (W smem constant after init -> hoist safe).

#define T_STEPS 512
#define BATCH   256
#define IN_SZ   64
#define HID     256
#define NTHR    512
#define NCTA    (BATCH / 2)

#define NGROUP        4
#define ROWS_PER_G    80
#define CHUNKS_PER_G  12          // 48 smem W rows per group
#define SMEM_ROWS_G   48
#define RF_U64        16          // 32 reg W rows per group (per j)
#define RF_ITERS      (RF_U64 / 2)              // 8
#define NSLOTS        (CHUNKS_PER_G + RF_ITERS) // 20
#define TOTAL_CHUNKS  (NGROUP * CHUNKS_PER_G)   // 48

typedef unsigned long long u64;

#define SMEM_W_BYTES   (TOTAL_CHUNKS * HID * 16)     // 196608
#define HAUG_STRIDE    88                            // 80 rows + pad (16B mult)
#define HAUG_OFF       SMEM_W_BYTES
#define RED_OFF        (HAUG_OFF + NGROUP * 2 * HAUG_STRIDE * 4)   // +2816
#define RED_PAR_FLOATS (2 * NGROUP * HID)            // 2048 per parity
#define SMEM_TOTAL     (RED_OFF + 2 * RED_PAR_FLOATS * 4)          // 215808

// slot schedule: true = RF iter, false = chunk iter.  Pattern (r c c r c) x4
// -> 8 RF + 12 chunk slots, evenly mixed.
__device__ constexpr bool IS_RF[NSLOTS] = {
    true, false, false, true, false,
    true, false, false, true, false,
    true, false, false, true, false,
    true, false, false, true, false
};

__device__ __forceinline__ u64 fma2(u64 a, u64 b, u64 c) {
    u64 d;
    asm("fma.rn.f32x2 %0, %1, %2, %3;" : "=l"(d) : "l"(a), "l"(b), "l"(c));
    return d;
}
__device__ __forceinline__ float sum2(u64 a) {
    float lo, hi;
    asm("mov.b64 {%0, %1}, %2;" : "=f"(lo), "=f"(hi) : "l"(a));
    return lo + hi;
}
__device__ __forceinline__ const float* wrow(const float* Win, const float* Whh,
                                             int j, int aug) {
    return (aug < IN_SZ) ? &Win[j * IN_SZ + aug] : &Whh[j * HID + (aug - IN_SZ)];
}

__global__ void __launch_bounds__(NTHR, 1)
ctrnn_ilv_kernel(const float* __restrict__ x,
                 const float* __restrict__ h0,
                 const float* __restrict__ noise,
                 const float* __restrict__ Win,
                 const float* __restrict__ bin,
                 const float* __restrict__ Whh,
                 const float* __restrict__ bhh,
                 float* __restrict__ out,
                 float* __restrict__ hlast)
{
    extern __shared__ unsigned char smem_raw[];
    ulonglong2* Wsm = reinterpret_cast<ulonglong2*>(smem_raw);
    float* haug = reinterpret_cast<float*>(smem_raw + HAUG_OFF);  // [4][2][88]
    float* red  = reinterpret_cast<float*>(smem_raw + RED_OFF);   // [2][2][4][256]

    const int tid = threadIdx.x;
    const int g   = tid >> 7;          // k-group 0..3
    const int jl  = tid & 127;
    const int j0  = jl;
    const int j1  = jl + 128;
    const int b0  = blockIdx.x * 2;
    const int b1  = b0 + 1;

    // ---- stage W smem: chunk i covers aug rows 80g+4i..+3, cols j0 and j1 ----
    for (int i = 0; i < CHUNKS_PER_G; ++i) {
        const int aug = ROWS_PER_G * g + 4 * i;
        *reinterpret_cast<float4*>(&Wsm[(g * CHUNKS_PER_G + i) * HID + j0]) =
            *reinterpret_cast<const float4*>(wrow(Win, Whh, j0, aug));
        *reinterpret_cast<float4*>(&Wsm[(g * CHUNKS_PER_G + i) * HID + j1]) =
            *reinterpret_cast<const float4*>(wrow(Win, Whh, j1, aug));
    }

    // ---- register W rows: aug 80g+48 .. 80g+79 (32 rows = 16 u64 per j) ----
    u64 wr0[RF_U64], wr1[RF_U64];
    #pragma unroll
    for (int m = 0; m < RF_U64; ++m) {
        const int aug = ROWS_PER_G * g + SMEM_ROWS_G + 2 * m;
        wr0[m] = *reinterpret_cast<const u64*>(wrow(Win, Whh, j0, aug));
        wr1[m] = *reinterpret_cast<const u64*>(wrow(Win, Whh, j1, aug));
    }

    // ---- finalize identity ----
    const int  nrows = (g == 0) ? 16 : 80;
    const bool act   = jl < nrows;
    const int  myj   = (g == 0) ? jl : ((g == 1 ? 16 : (g == 2 ? 96 : 176)) + jl);
    const int  lidx  = (g == 0) ? 64 + jl : jl;   // index within own slice
    const float bsum = act ? (bin[myj] + bhh[myj]) : 0.f;

    // x staging identity (group 0 only)
    const int xb = jl >> 6;
    const int xi = jl & 63;
    const int xbatch = xb ? b1 : b0;

    float* myA = haug + (g * 2 + 0) * HAUG_STRIDE;
    float* myB = haug + (g * 2 + 1) * HAUG_STRIDE;

    // ---- initial staging of own slice ----
    if (act) {
        myA[lidx] = h0[b0 * HID + myj];
        myB[lidx] = h0[b1 * HID + myj];
    }
    if (g == 0)
        (xb ? myB : myA)[xi] = x[(size_t)xbatch * IN_SZ + xi];
    float nz = act ? (noise[myj] + bsum) : 0.f;
    __syncthreads();

    const ulonglong2* wp0 = Wsm + (size_t)(g * CHUNKS_PER_G) * HID + j0;
    const ulonglong2* wp1 = Wsm + (size_t)(g * CHUNKS_PER_G) * HID + j1;

    // ---- prime depth-1 W lookahead (chunk 0) ----
    ulonglong2 wb0 = wp0[0];
    ulonglong2 wb1 = wp1[0];

    for (int t = 0; t < T_STEPS; ++t) {
        float* redp = red + (t & 1) * RED_PAR_FLOATS;

        // prefetch next x / noise
        const int tn = (t + 1 < T_STEPS) ? t + 1 : t;
        float xn = 0.f, nzn = 0.f;
        if (g == 0) xn = x[((size_t)tn * BATCH + xbatch) * IN_SZ + xi];
        if (act)    nzn = noise[(size_t)tn * HID + myj] + bsum;

        // ---- interleaved FMA phase: 4 accumulator chains (batch x j) ----
        u64 aA0 = 0, aA1 = 0, aB0 = 0, aB1 = 0;
        int ci = 0, ri = 0;

        #pragma unroll
        for (int k = 0; k < NSLOTS; ++k) {
            if (IS_RF[k]) {
                // RF iter ri: rows +48+4*ri, weights in registers
                ulonglong2 ha = *reinterpret_cast<const ulonglong2*>(&myA[SMEM_ROWS_G + 4 * ri]);
                ulonglong2 hb = *reinterpret_cast<const ulonglong2*>(&myB[SMEM_ROWS_G + 4 * ri]);
                aA0 = fma2(wr0[2 * ri], ha.x, aA0);  aA0 = fma2(wr0[2 * ri + 1], ha.y, aA0);
                aA1 = fma2(wr1[2 * ri], ha.x, aA1);  aA1 = fma2(wr1[2 * ri + 1], ha.y, aA1);
                aB0 = fma2(wr0[2 * ri], hb.x, aB0);  aB0 = fma2(wr0[2 * ri + 1], hb.y, aB0);
                aB1 = fma2(wr1[2 * ri], hb.x, aB1);  aB1 = fma2(wr1[2 * ri + 1], hb.y, aB1);
                ++ri;
            } else {
                // chunk iter ci: consume buffered W, issue chunk (ci+1)%12;
                // the last chunk slot fetches NEXT step's chunk 0 pre-barrier.
                const ulonglong2 w0 = wb0;
                const ulonglong2 w1 = wb1;
                int nc = ci + 1;
                if (nc >= CHUNKS_PER_G) nc = 0;
                wb0 = wp0[(size_t)nc * HID];
                wb1 = wp1[(size_t)nc * HID];

                ulonglong2 ha = *reinterpret_cast<const ulonglong2*>(&myA[4 * ci]);
                ulonglong2 hb = *reinterpret_cast<const ulonglong2*>(&myB[4 * ci]);
                aA0 = fma2(w0.x, ha.x, aA0);  aA0 = fma2(w0.y, ha.y, aA0);
                aA1 = fma2(w1.x, ha.x, aA1);  aA1 = fma2(w1.y, ha.y, aA1);
                aB0 = fma2(w0.x, hb.x, aB0);  aB0 = fma2(w0.y, hb.y, aB0);
                aB1 = fma2(w1.x, hb.x, aB1);  aB1 = fma2(w1.y, hb.y, aB1);
                ++ci;
            }
        }

        redp[(0 * NGROUP + g) * HID + j0] = sum2(aA0);
        redp[(0 * NGROUP + g) * HID + j1] = sum2(aA1);
        redp[(1 * NGROUP + g) * HID + j0] = sum2(aB0);
        redp[(1 * NGROUP + g) * HID + j1] = sum2(aB1);
        __syncthreads();                       // the ONE full-CTA barrier

        // ---- finalize own j-range ----
        if (act) {
            const float* rA = redp;
            const float* rB = redp + NGROUP * HID;
            const float sA = rA[0 * HID + myj] + rA[1 * HID + myj]
                           + rA[2 * HID + myj] + rA[3 * HID + myj];
            const float sB = rB[0 * HID + myj] + rB[1 * HID + myj]
                           + rB[2 * HID + myj] + rB[3 * HID + myj];
            const float hnA = fmaxf(myA[lidx] * 0.8f + (sA + nz) * 0.2f, 0.f);
            const float hnB = fmaxf(myB[lidx] * 0.8f + (sB + nz) * 0.2f, 0.f);
            if (out) {
                out[((size_t)t * BATCH + b0) * HID + myj] = hnA;
                out[((size_t)t * BATCH + b1) * HID + myj] = hnB;
            }
            myA[lidx] = hnA;
            myB[lidx] = hnB;
        }
        if (g == 0)
            (xb ? myB : myA)[xi] = xn;
        nz = nzn;

        asm volatile("bar.sync %0, %1;" :: "r"(g + 1), "r"(128) : "memory");
    }

    if (hlast && act) {
        hlast[b0 * HID + myj] = myA[lidx];
        hlast[b1 * HID + myj] = myB[lidx];
    }
}

extern "C" void kernel_launch(void* const* d_in, const int* in_sizes, int n_in,
                              void* d_out, int out_size)
{
    const float* x     = (const float*)d_in[0];   // [512,256,64]
    const float* h0    = (const float*)d_in[1];   // [256,256]
    const float* noise = (const float*)d_in[2];   // [512,256]
    const float* Win   = (const float*)d_in[3];   // [256,64]
    const float* bin   = (const float*)d_in[4];   // [256]
    const float* Whh   = (const float*)d_in[5];   // [256,256]
    const float* bhh   = (const float*)d_in[6];   // [256]

    const size_t TBH = (size_t)T_STEPS * BATCH * HID;
    const size_t BH  = (size_t)BATCH * HID;

    float* out   = nullptr;
    float* hlast = nullptr;
    if ((size_t)out_size >= TBH) {
        out = (float*)d_out;
        if ((size_t)out_size >= TBH + BH) hlast = (float*)d_out + TBH;
    } else {
        hlast = (float*)d_out;
    }

    static bool attr_set = false;
    if (!attr_set) {
        cudaFuncSetAttribute(ctrnn_ilv_kernel,
                             cudaFuncAttributeMaxDynamicSharedMemorySize, SMEM_TOTAL);
        attr_set = true;
    }

    ctrnn_ilv_kernel<<<NCTA, NTHR, SMEM_TOTAL>>>(
        x, h0, noise, Win, bin, Whh, bhh, out, hlast);
}

// round 11
// speedup vs baseline: 1.0894x; 1.0302x over previous
#include <cuda_runtime.h>
#include <cstdint>
#include <cstddef>

// CTRNN round 11: two-kernel split.
//  Kernel 1 (pre-pass): pre[t,b,j] = x[t,b,:]@Win[j,:] + bin[j] + bhh[j]
//                        + noise[t,j]  -- bulk GEMM, Win register-resident.
//  Kernel 2 (recurrent): h[t+1] = relu(0.8h + 0.2(h@Whh^T + pre[t])),
//    aug K = 256 (Whh only). 128 CTAs x 512 threads, 2 batches/CTA.
//    4 k-groups x 64 rows: 32 rows via smem (8 chunks, [chunk][j] 16B slots),
//    32 rows register-resident (16 u64 per j); 2 outputs j0/j1 per thread.
//    Interleaved (chunk, RF) slot schedule + depth-1 cross-barrier W
//    lookahead. Group g finalizes j [64g, 64g+64) (its own slice rows),
//    reading pre[t] via LDG prefetched at step top (hidden under FMA phase).

#define T_STEPS 512
#define BATCH   256
#define IN_SZ   64
#define HID     256
#define NTHR    512
#define NCTA    (BATCH / 2)

#define NGROUP        4
#define ROWS_PER_G    64
#define CHUNKS_PER_G  8           // 32 smem W rows per group
#define SMEM_ROWS_G   32
#define RF_U64        16          // 32 reg W rows per group (per j)
#define NSLOTS        (CHUNKS_PER_G + RF_U64 / 2)   // 16
#define TOTAL_CHUNKS  (NGROUP * CHUNKS_PER_G)       // 32

typedef unsigned long long u64;

#define SMEM_W_BYTES   (TOTAL_CHUNKS * HID * 16)     // 131072
#define HAUG_STRIDE    72                            // 64 rows + pad (16B mult)
#define HAUG_OFF       SMEM_W_BYTES
#define RED_OFF        (HAUG_OFF + NGROUP * 2 * HAUG_STRIDE * 4)   // +2304
#define RED_PAR_FLOATS (2 * NGROUP * HID)            // 2048 per parity
#define SMEM_TOTAL     (RED_OFF + 2 * RED_PAR_FLOATS * 4)          // 149760

// 134 MB scratch for pre[t][b][j] (device-global array: the sanctioned
// scratch mechanism; no allocation APIs anywhere).
__device__ float g_pre[(size_t)T_STEPS * BATCH * HID];

__device__ __forceinline__ u64 fma2(u64 a, u64 b, u64 c) {
    u64 d;
    asm("fma.rn.f32x2 %0, %1, %2, %3;" : "=l"(d) : "l"(a), "l"(b), "l"(c));
    return d;
}
__device__ __forceinline__ u64 add2(u64 a, u64 b) {
    u64 d;
    asm("add.rn.f32x2 %0, %1, %2;" : "=l"(d) : "l"(a), "l"(b));
    return d;
}
__device__ __forceinline__ float sum2(u64 a) {
    float lo, hi;
    asm("mov.b64 {%0, %1}, %2;" : "=f"(lo), "=f"(hi) : "l"(a));
    return lo + hi;
}

// ---------------------------------------------------------------------------
// Kernel 1: pre-pass. 512 CTAs x 256 threads; CTA handles 256 flattened
// (t*B + b) rows in 16 blocks of 16; thread = output unit j with Win[j,:]
// in registers (32 u64). x rows staged in smem, read as uniform LDS.128.
// ---------------------------------------------------------------------------
#define PP_NCTA 512
#define PP_THR  256
#define PP_BLK_ROWS 16

__global__ void __launch_bounds__(PP_THR)
ctrnn_prepass(const float* __restrict__ x,
              const float* __restrict__ noise,
              const float* __restrict__ Win,
              const float* __restrict__ bin,
              const float* __restrict__ bhh)
{
    __shared__ float xs[PP_BLK_ROWS * IN_SZ];    // 4 KB

    const int j = threadIdx.x;
    u64 w[IN_SZ / 2];
    #pragma unroll
    for (int m = 0; m < IN_SZ / 2; ++m)
        w[m] = *reinterpret_cast<const u64*>(&Win[j * IN_SZ + 2 * m]);
    const float bias = bin[j] + bhh[j];

    const size_t cta_row0 = (size_t)blockIdx.x * 256;

    for (int blk = 0; blk < 16; ++blk) {
        const size_t row0 = cta_row0 + (size_t)blk * PP_BLK_ROWS;
        __syncthreads();   // previous block's xs reads done
        // 16 rows x 64 floats = 256 float4; thread j loads float4 #j
        reinterpret_cast<float4*>(xs)[j] =
            reinterpret_cast<const float4*>(x + row0 * IN_SZ)[j];
        __syncthreads();

        #pragma unroll 2
        for (int r = 0; r < PP_BLK_ROWS; ++r) {
            const size_t row = row0 + r;
            const int t = (int)(row >> 8);       // row / BATCH
            const ulonglong2* xr =
                reinterpret_cast<const ulonglong2*>(&xs[r * IN_SZ]);
            u64 a0 = 0, a1 = 0;
            #pragma unroll
            for (int m = 0; m < IN_SZ / 4; ++m) {   // 16 x LDS.128 uniform
                ulonglong2 xv = xr[m];
                a0 = fma2(w[2 * m],     xv.x, a0);
                a1 = fma2(w[2 * m + 1], xv.y, a1);
            }
            g_pre[row * HID + j] = sum2(add2(a0, a1))
                                 + noise[(size_t)t * HID + j] + bias;
        }
    }
}

// ---------------------------------------------------------------------------
// Kernel 2: recurrent loop (aug K = 256, Whh only).
// ---------------------------------------------------------------------------
__global__ void __launch_bounds__(NTHR, 1)
ctrnn_rec_kernel(const float* __restrict__ h0,
                 const float* __restrict__ Whh,
                 float* __restrict__ out,
                 float* __restrict__ hlast)
{
    extern __shared__ unsigned char smem_raw[];
    ulonglong2* Wsm = reinterpret_cast<ulonglong2*>(smem_raw);
    float* haug = reinterpret_cast<float*>(smem_raw + HAUG_OFF);  // [4][2][72]
    float* red  = reinterpret_cast<float*>(smem_raw + RED_OFF);   // [2][2][4][256]

    const int tid = threadIdx.x;
    const int g   = tid >> 7;          // k-group 0..3
    const int jl  = tid & 127;
    const int j0  = jl;
    const int j1  = jl + 128;
    const int b0  = blockIdx.x * 2;
    const int b1  = b0 + 1;

    // ---- stage W smem: chunk i covers Whh cols 64g+4i..+3, rows j0/j1 ----
    for (int i = 0; i < CHUNKS_PER_G; ++i) {
        const int col = ROWS_PER_G * g + 4 * i;
        *reinterpret_cast<float4*>(&Wsm[(g * CHUNKS_PER_G + i) * HID + j0]) =
            *reinterpret_cast<const float4*>(&Whh[j0 * HID + col]);
        *reinterpret_cast<float4*>(&Wsm[(g * CHUNKS_PER_G + i) * HID + j1]) =
            *reinterpret_cast<const float4*>(&Whh[j1 * HID + col]);
    }

    // ---- register W rows: Whh cols 64g+32 .. 64g+63 (16 u64 per j) ----
    u64 wr0[RF_U64], wr1[RF_U64];
    #pragma unroll
    for (int m = 0; m < RF_U64; ++m) {
        const int col = ROWS_PER_G * g + SMEM_ROWS_G + 2 * m;
        wr0[m] = *reinterpret_cast<const u64*>(&Whh[j0 * HID + col]);
        wr1[m] = *reinterpret_cast<const u64*>(&Whh[j1 * HID + col]);
    }

    // ---- finalize identity: group g owns j [64g, 64g+64) ----
    const bool act = jl < ROWS_PER_G;
    const int  myj = ROWS_PER_G * g + jl;       // valid when act

    float* myA = haug + (g * 2 + 0) * HAUG_STRIDE;
    float* myB = haug + (g * 2 + 1) * HAUG_STRIDE;

    // ---- initial h staging ----
    if (act) {
        myA[jl] = h0[b0 * HID + myj];
        myB[jl] = h0[b1 * HID + myj];
    }
    __syncthreads();

    const ulonglong2* wp0 = Wsm + (size_t)(g * CHUNKS_PER_G) * HID + j0;
    const ulonglong2* wp1 = Wsm + (size_t)(g * CHUNKS_PER_G) * HID + j1;

    // ---- prime depth-1 W lookahead (chunk 0) ----
    ulonglong2 wb0 = wp0[0];
    ulonglong2 wb1 = wp1[0];

    for (int t = 0; t < T_STEPS; ++t) {
        float* redp = red + (t & 1) * RED_PAR_FLOATS;

        // prefetch this step's static pre-activation (used after the CTA
        // barrier; DRAM latency hidden under the ~2K-cycle FMA phase)
        float preA = 0.f, preB = 0.f;
        if (act) {
            preA = g_pre[((size_t)t * BATCH + b0) * HID + myj];
            preB = g_pre[((size_t)t * BATCH + b1) * HID + myj];
        }

        // ---- interleaved FMA phase: (c r) x 8 slots ----
        u64 aA0 = 0, aA1 = 0, aB0 = 0, aB1 = 0;
        int ci = 0, ri = 0;

        #pragma unroll
        for (int k = 0; k < NSLOTS; ++k) {
            if (k & 1) {
                // RF slot ri: local rows 32+4*ri
                ulonglong2 ha = *reinterpret_cast<const ulonglong2*>(&myA[SMEM_ROWS_G + 4 * ri]);
                ulonglong2 hb = *reinterpret_cast<const ulonglong2*>(&myB[SMEM_ROWS_G + 4 * ri]);
                aA0 = fma2(wr0[2 * ri], ha.x, aA0);  aA0 = fma2(wr0[2 * ri + 1], ha.y, aA0);
                aA1 = fma2(wr1[2 * ri], ha.x, aA1);  aA1 = fma2(wr1[2 * ri + 1], ha.y, aA1);
                aB0 = fma2(wr0[2 * ri], hb.x, aB0);  aB0 = fma2(wr0[2 * ri + 1], hb.y, aB0);
                aB1 = fma2(wr1[2 * ri], hb.x, aB1);  aB1 = fma2(wr1[2 * ri + 1], hb.y, aB1);
                ++ri;
            } else {
                // chunk slot ci: consume buffered W, issue chunk (ci+1)%8;
                // last chunk slot fetches NEXT step's chunk 0 pre-barrier
                // (W smem constant after init -> hoist safe).
                const ulonglong2 w0 = wb0;
                const ulonglong2 w1 = wb1;
                int nc = ci + 1;
                if (nc >= CHUNKS_PER_G) nc = 0;
                wb0 = wp0[(size_t)nc * HID];
                wb1 = wp1[(size_t)nc * HID];

                ulonglong2 ha = *reinterpret_cast<const ulonglong2*>(&myA[4 * ci]);
                ulonglong2 hb = *reinterpret_cast<const ulonglong2*>(&myB[4 * ci]);
                aA0 = fma2(w0.x, ha.x, aA0);  aA0 = fma2(w0.y, ha.y, aA0);
                aA1 = fma2(w1.x, ha.x, aA1);  aA1 = fma2(w1.y, ha.y, aA1);
                aB0 = fma2(w0.x, hb.x, aB0);  aB0 = fma2(w0.y, hb.y, aB0);
                aB1 = fma2(w1.x, hb.x, aB1);  aB1 = fma2(w1.y, hb.y, aB1);
                ++ci;
            }
        }

        redp[(0 * NGROUP + g) * HID + j0] = sum2(aA0);
        redp[(0 * NGROUP + g) * HID + j1] = sum2(aA1);
        redp[(1 * NGROUP + g) * HID + j0] = sum2(aB0);
        redp[(1 * NGROUP + g) * HID + j1] = sum2(aB1);
        __syncthreads();                       // the ONE full-CTA barrier

        // ---- finalize own j-range ----
        if (act) {
            const float* rA = redp;
            const float* rB = redp + NGROUP * HID;
            const float sA = rA[0 * HID + myj] + rA[1 * HID + myj]
                           + rA[2 * HID + myj] + rA[3 * HID + myj];
            const float sB = rB[0 * HID + myj] + rB[1 * HID + myj]
                           + rB[2 * HID + myj] + rB[3 * HID + myj];
            const float hnA = fmaxf(myA[jl] * 0.8f + (sA + preA) * 0.2f, 0.f);
            const float hnB = fmaxf(myB[jl] * 0.8f + (sB + preB) * 0.2f, 0.f);
            if (out) {
                out[((size_t)t * BATCH + b0) * HID + myj] = hnA;
                out[((size_t)t * BATCH + b1) * HID + myj] = hnB;
            }
            myA[jl] = hnA;
            myB[jl] = hnB;
        }

        asm volatile("bar.sync %0, %1;" :: "r"(g + 1), "r"(128) : "memory");
    }

    if (hlast && act) {
        hlast[b0 * HID + myj] = myA[jl];
        hlast[b1 * HID + myj] = myB[jl];
    }
}

extern "C" void kernel_launch(void* const* d_in, const int* in_sizes, int n_in,
                              void* d_out, int out_size)
{
    const float* x     = (const float*)d_in[0];   // [512,256,64]
    const float* h0    = (const float*)d_in[1];   // [256,256]
    const float* noise = (const float*)d_in[2];   // [512,256]
    const float* Win   = (const float*)d_in[3];   // [256,64]
    const float* bin   = (const float*)d_in[4];   // [256]
    const float* Whh   = (const float*)d_in[5];   // [256,256]
    const float* bhh   = (const float*)d_in[6];   // [256]

    const size_t TBH = (size_t)T_STEPS * BATCH * HID;
    const size_t BH  = (size_t)BATCH * HID;

    float* out   = nullptr;
    float* hlast = nullptr;
    if ((size_t)out_size >= TBH) {
        out = (float*)d_out;
        if ((size_t)out_size >= TBH + BH) hlast = (float*)d_out + TBH;
    } else {
        hlast = (float*)d_out;
    }

    static bool attr_set = false;
    if (!attr_set) {
        cudaFuncSetAttribute(ctrnn_rec_kernel,
                             cudaFuncAttributeMaxDynamicSharedMemorySize, SMEM_TOTAL);
        attr_set = true;
    }

    ctrnn_prepass<<<PP_NCTA, PP_THR>>>(x, noise, Win, bin, bhh);
    ctrnn_rec_kernel<<<NCTA, NTHR, SMEM_TOTAL>>>(h0, Whh, out, hlast);
}

// round 12
// speedup vs baseline: 1.1470x; 1.0529x over previous
#include <cuda_runtime.h>
#include <cstdint>
#include <cstddef>

// CTRNN round 12: R11 recurrent kernel (unchanged, matched its model) +
// rebuilt pre-pass:
//   * persistent grid 296 = 2 CTAs/SM exactly (no wave quantization),
//     round-robin over 8192 16-row blocks
//   * double-buffered x staging: next block's LDG issues at top of current
//     block's compute; one syncthreads per block; DRAM latency hidden
//   * noise+bias hoisted per block (t constant within a 16-row block)

#define T_STEPS 512
#define BATCH   256
#define IN_SZ   64
#define HID     256
#define NTHR    512
#define NCTA    (BATCH / 2)

#define NGROUP        4
#define ROWS_PER_G    64
#define CHUNKS_PER_G  8           // 32 smem W rows per group
#define SMEM_ROWS_G   32
#define RF_U64        16          // 32 reg W rows per group (per j)
#define NSLOTS        (CHUNKS_PER_G + RF_U64 / 2)   // 16
#define TOTAL_CHUNKS  (NGROUP * CHUNKS_PER_G)       // 32

typedef unsigned long long u64;

#define SMEM_W_BYTES   (TOTAL_CHUNKS * HID * 16)     // 131072
#define HAUG_STRIDE    72                            // 64 rows + pad (16B mult)
#define HAUG_OFF       SMEM_W_BYTES
#define RED_OFF        (HAUG_OFF + NGROUP * 2 * HAUG_STRIDE * 4)   // +2304
#define RED_PAR_FLOATS (2 * NGROUP * HID)            // 2048 per parity
#define SMEM_TOTAL     (RED_OFF + 2 * RED_PAR_FLOATS * 4)          // 149760

// 134 MB scratch for pre[t][b][j] (device-global array: sanctioned scratch).
__device__ float g_pre[(size_t)T_STEPS * BATCH * HID];

__device__ __forceinline__ u64 fma2(u64 a, u64 b, u64 c) {
    u64 d;
    asm("fma.rn.f32x2 %0, %1, %2, %3;" : "=l"(d) : "l"(a), "l"(b), "l"(c));
    return d;
}
__device__ __forceinline__ u64 add2(u64 a, u64 b) {
    u64 d;
    asm("add.rn.f32x2 %0, %1, %2;" : "=l"(d) : "l"(a), "l"(b));
    return d;
}
__device__ __forceinline__ float sum2(u64 a) {
    float lo, hi;
    asm("mov.b64 {%0, %1}, %2;" : "=f"(lo), "=f"(hi) : "l"(a));
    return lo + hi;
}

// ---------------------------------------------------------------------------
// Kernel 1: pre-pass v2.
// 296 CTAs x 256 threads (2 CTAs/SM). Thread = output unit j, Win[j,:] in
// 32 u64 registers. Blocks of 16 flattened (t*B+b) rows; x row data staged
// through double-buffered smem (one 4KB buffer per phase).
// ---------------------------------------------------------------------------
#define PP_NCTA 296
#define PP_THR  256
#define PP_BLK_ROWS 16
#define PP_NBLK (T_STEPS * BATCH / PP_BLK_ROWS)     // 8192

__global__ void __launch_bounds__(PP_THR, 2)
ctrnn_prepass(const float* __restrict__ x,
              const float* __restrict__ noise,
              const float* __restrict__ Win,
              const float* __restrict__ bin,
              const float* __restrict__ bhh)
{
    __shared__ float xs[2][PP_BLK_ROWS * IN_SZ];    // 2 x 4 KB

    const int j = threadIdx.x;
    u64 w[IN_SZ / 2];
    #pragma unroll
    for (int m = 0; m < IN_SZ / 2; ++m)
        w[m] = *reinterpret_cast<const u64*>(&Win[j * IN_SZ + 2 * m]);
    const float bias = bin[j] + bhh[j];

    int blk = blockIdx.x;
    // prime buffer 0 with the first assigned block's 16 x-rows
    // (16 rows x 64 floats = 256 float4; thread j carries float4 #j)
    reinterpret_cast<float4*>(xs[0])[j] =
        reinterpret_cast<const float4*>(x + (size_t)blk * PP_BLK_ROWS * IN_SZ)[j];
    __syncthreads();
    int cur = 0;

    while (true) {
        const int nblk = blk + PP_NCTA;
        const bool has_next = nblk < PP_NBLK;

        // issue next block's x LDG early; latency hides under this block's
        // ~800-cycle compute body
        float4 vn;
        if (has_next)
            vn = reinterpret_cast<const float4*>(
                     x + (size_t)nblk * PP_BLK_ROWS * IN_SZ)[j];

        // t is constant across a 16-row block (rows blk*16 .. blk*16+15,
        // t = row/256 = blk/16): hoist noise+bias
        const int   t   = blk >> 4;
        const float nb  = noise[(size_t)t * HID + j] + bias;
        const size_t row0 = (size_t)blk * PP_BLK_ROWS;

        #pragma unroll 4
        for (int r = 0; r < PP_BLK_ROWS; ++r) {
            const ulonglong2* xr =
                reinterpret_cast<const ulonglong2*>(&xs[cur][r * IN_SZ]);
            u64 a0 = 0, a1 = 0;
            #pragma unroll
            for (int m = 0; m < IN_SZ / 4; ++m) {   // 16 uniform LDS.128
                ulonglong2 xv = xr[m];
                a0 = fma2(w[2 * m],     xv.x, a0);
                a1 = fma2(w[2 * m + 1], xv.y, a1);
            }
            g_pre[(row0 + r) * HID + j] = sum2(add2(a0, a1)) + nb;
        }

        if (!has_next) break;
        // stage next block into the other buffer. Safe with ONE bar/block:
        // all reads of xs[cur^1] (from the previous iteration) completed
        // before the previous iteration's barrier; this STS is after it.
        reinterpret_cast<float4*>(xs[cur ^ 1])[j] = vn;
        __syncthreads();
        cur ^= 1;
        blk = nblk;
    }
}

// ---------------------------------------------------------------------------
// Kernel 2: recurrent loop (aug K = 256, Whh only) — unchanged from R11.
// ---------------------------------------------------------------------------
__global__ void __launch_bounds__(NTHR, 1)
ctrnn_rec_kernel(const float* __restrict__ h0,
                 const float* __restrict__ Whh,
                 float* __restrict__ out,
                 float* __restrict__ hlast)
{
    extern __shared__ unsigned char smem_raw[];
    ulonglong2* Wsm = reinterpret_cast<ulonglong2*>(smem_raw);
    float* haug = reinterpret_cast<float*>(smem_raw + HAUG_OFF);  // [4][2][72]
    float* red  = reinterpret_cast<float*>(smem_raw + RED_OFF);   // [2][2][4][256]

    const int tid = threadIdx.x;
    const int g   = tid >> 7;          // k-group 0..3
    const int jl  = tid & 127;
    const int j0  = jl;
    const int j1  = jl + 128;
    const int b0  = blockIdx.x * 2;
    const int b1  = b0 + 1;

    // ---- stage W smem: chunk i covers Whh cols 64g+4i..+3, rows j0/j1 ----
    for (int i = 0; i < CHUNKS_PER_G; ++i) {
        const int col = ROWS_PER_G * g + 4 * i;
        *reinterpret_cast<float4*>(&Wsm[(g * CHUNKS_PER_G + i) * HID + j0]) =
            *reinterpret_cast<const float4*>(&Whh[j0 * HID + col]);
        *reinterpret_cast<float4*>(&Wsm[(g * CHUNKS_PER_G + i) * HID + j1]) =
            *reinterpret_cast<const float4*>(&Whh[j1 * HID + col]);
    }

    // ---- register W rows: Whh cols 64g+32 .. 64g+63 (16 u64 per j) ----
    u64 wr0[RF_U64], wr1[RF_U64];
    #pragma unroll
    for (int m = 0; m < RF_U64; ++m) {
        const int col = ROWS_PER_G * g + SMEM_ROWS_G + 2 * m;
        wr0[m] = *reinterpret_cast<const u64*>(&Whh[j0 * HID + col]);
        wr1[m] = *reinterpret_cast<const u64*>(&Whh[j1 * HID + col]);
    }

    // ---- finalize identity: group g owns j [64g, 64g+64) ----
    const bool act = jl < ROWS_PER_G;
    const int  myj = ROWS_PER_G * g + jl;       // valid when act

    float* myA = haug + (g * 2 + 0) * HAUG_STRIDE;
    float* myB = haug + (g * 2 + 1) * HAUG_STRIDE;

    // ---- initial h staging ----
    if (act) {
        myA[jl] = h0[b0 * HID + myj];
        myB[jl] = h0[b1 * HID + myj];
    }
    __syncthreads();

    const ulonglong2* wp0 = Wsm + (size_t)(g * CHUNKS_PER_G) * HID + j0;
    const ulonglong2* wp1 = Wsm + (size_t)(g * CHUNKS_PER_G) * HID + j1;

    // ---- prime depth-1 W lookahead (chunk 0) ----
    ulonglong2 wb0 = wp0[0];
    ulonglong2 wb1 = wp1[0];

    for (int t = 0; t < T_STEPS; ++t) {
        float* redp = red + (t & 1) * RED_PAR_FLOATS;

        // prefetch this step's static pre-activation (consumed after the CTA
        // barrier; DRAM latency hidden under the FMA phase)
        float preA = 0.f, preB = 0.f;
        if (act) {
            preA = g_pre[((size_t)t * BATCH + b0) * HID + myj];
            preB = g_pre[((size_t)t * BATCH + b1) * HID + myj];
        }

        // ---- interleaved FMA phase: (c r) x 8 slots ----
        u64 aA0 = 0, aA1 = 0, aB0 = 0, aB1 = 0;
        int ci = 0, ri = 0;

        #pragma unroll
        for (int k = 0; k < NSLOTS; ++k) {
            if (k & 1) {
                // RF slot ri: local rows 32+4*ri
                ulonglong2 ha = *reinterpret_cast<const ulonglong2*>(&myA[SMEM_ROWS_G + 4 * ri]);
                ulonglong2 hb = *reinterpret_cast<const ulonglong2*>(&myB[SMEM_ROWS_G + 4 * ri]);
                aA0 = fma2(wr0[2 * ri], ha.x, aA0);  aA0 = fma2(wr0[2 * ri + 1], ha.y, aA0);
                aA1 = fma2(wr1[2 * ri], ha.x, aA1);  aA1 = fma2(wr1[2 * ri + 1], ha.y, aA1);
                aB0 = fma2(wr0[2 * ri], hb.x, aB0);  aB0 = fma2(wr0[2 * ri + 1], hb.y, aB0);
                aB1 = fma2(wr1[2 * ri], hb.x, aB1);  aB1 = fma2(wr1[2 * ri + 1], hb.y, aB1);
                ++ri;
            } else {
                // chunk slot ci: consume buffered W, issue chunk (ci+1)%8;
                // last chunk slot fetches NEXT step's chunk 0 pre-barrier
                // (W smem constant after init -> hoist safe).
                const ulonglong2 w0 = wb0;
                const ulonglong2 w1 = wb1;
                int nc = ci + 1;
                if (nc >= CHUNKS_PER_G) nc = 0;
                wb0 = wp0[(size_t)nc * HID];
                wb1 = wp1[(size_t)nc * HID];

                ulonglong2 ha = *reinterpret_cast<const ulonglong2*>(&myA[4 * ci]);
                ulonglong2 hb = *reinterpret_cast<const ulonglong2*>(&myB[4 * ci]);
                aA0 = fma2(w0.x, ha.x, aA0);  aA0 = fma2(w0.y, ha.y, aA0);
                aA1 = fma2(w1.x, ha.x, aA1);  aA1 = fma2(w1.y, ha.y, aA1);
                aB0 = fma2(w0.x, hb.x, aB0);  aB0 = fma2(w0.y, hb.y, aB0);
                aB1 = fma2(w1.x, hb.x, aB1);  aB1 = fma2(w1.y, hb.y, aB1);
                ++ci;
            }
        }

        redp[(0 * NGROUP + g) * HID + j0] = sum2(aA0);
        redp[(0 * NGROUP + g) * HID + j1] = sum2(aA1);
        redp[(1 * NGROUP + g) * HID + j0] = sum2(aB0);
        redp[(1 * NGROUP + g) * HID + j1] = sum2(aB1);
        __syncthreads();                       // the ONE full-CTA barrier

        // ---- finalize own j-range ----
        if (act) {
            const float* rA = redp;
            const float* rB = redp + NGROUP * HID;
            const float sA = rA[0 * HID + myj] + rA[1 * HID + myj]
                           + rA[2 * HID + myj] + rA[3 * HID + myj];
            const float sB = rB[0 * HID + myj] + rB[1 * HID + myj]
                           + rB[2 * HID + myj] + rB[3 * HID + myj];
            const float hnA = fmaxf(myA[jl] * 0.8f + (sA + preA) * 0.2f, 0.f);
            const float hnB = fmaxf(myB[jl] * 0.8f + (sB + preB) * 0.2f, 0.f);
            if (out) {
                out[((size_t)t * BATCH + b0) * HID + myj] = hnA;
                out[((size_t)t * BATCH + b1) * HID + myj] = hnB;
            }
            myA[jl] = hnA;
            myB[jl] = hnB;
        }

        asm volatile("bar.sync %0, %1;" :: "r"(g + 1), "r"(128) : "memory");
    }

    if (hlast && act) {
        hlast[b0 * HID + myj] = myA[jl];
        hlast[b1 * HID + myj] = myB[jl];
    }
}

extern "C" void kernel_launch(void* const* d_in, const int* in_sizes, int n_in,
                              void* d_out, int out_size)
{
    const float* x     = (const float*)d_in[0];   // [512,256,64]
    const float* h0    = (const float*)d_in[1];   // [256,256]
    const float* noise = (const float*)d_in[2];   // [512,256]
    const float* Win   = (const float*)d_in[3];   // [256,64]
    const float* bin   = (const float*)d_in[4];   // [256]
    const float* Whh   = (const float*)d_in[5];   // [256,256]
    const float* bhh   = (const float*)d_in[6];   // [256]

    const size_t TBH = (size_t)T_STEPS * BATCH * HID;
    const size_t BH  = (size_t)BATCH * HID;

    float* out   = nullptr;
    float* hlast = nullptr;
    if ((size_t)out_size >= TBH) {
        out = (float*)d_out;
        if ((size_t)out_size >= TBH + BH) hlast = (float*)d_out + TBH;
    } else {
        hlast = (float*)d_out;
    }

    static bool attr_set = false;
    if (!attr_set) {
        cudaFuncSetAttribute(ctrnn_rec_kernel,
                             cudaFuncAttributeMaxDynamicSharedMemorySize, SMEM_TOTAL);
        attr_set = true;
    }

    ctrnn_prepass<<<PP_NCTA, PP_THR>>>(x, noise, Win, bin, bhh);
    ctrnn_rec_kernel<<<NCTA, NTHR, SMEM_TOTAL>>>(h0, Whh, out, hlast);
}

// round 13
// speedup vs baseline: 1.2108x; 1.0556x over previous
#include <cuda_runtime.h>
#include <cstdint>
#include <cstddef>

// CTRNN round 13:
//  * pre-pass v3: 2-row-paired inner loop -> 4 independent FMA chains and
//    2 independent LDS streams per iteration (fixes the serialized
//    LDS->FMA ladder that kept the two pipes from overlapping)
//  * rec kernel: finalize spread across all 4 warps of a group (one
//    (batch, j) item per thread instead of two items on half the threads)

#define T_STEPS 512
#define BATCH   256
#define IN_SZ   64
#define HID     256
#define NTHR    512
#define NCTA    (BATCH / 2)

#define NGROUP        4
#define ROWS_PER_G    64
#define CHUNKS_PER_G  8           // 32 smem W rows per group
#define SMEM_ROWS_G   32
#define RF_U64        16          // 32 reg W rows per group (per j)
#define NSLOTS        (CHUNKS_PER_G + RF_U64 / 2)   // 16
#define TOTAL_CHUNKS  (NGROUP * CHUNKS_PER_G)       // 32

typedef unsigned long long u64;

#define SMEM_W_BYTES   (TOTAL_CHUNKS * HID * 16)     // 131072
#define HAUG_STRIDE    72                            // 64 rows + pad (16B mult)
#define HAUG_OFF       SMEM_W_BYTES
#define RED_OFF        (HAUG_OFF + NGROUP * 2 * HAUG_STRIDE * 4)   // +2304
#define RED_PAR_FLOATS (2 * NGROUP * HID)            // 2048 per parity
#define SMEM_TOTAL     (RED_OFF + 2 * RED_PAR_FLOATS * 4)          // 149760

// 134 MB scratch for pre[t][b][j] (device-global array: sanctioned scratch).
__device__ float g_pre[(size_t)T_STEPS * BATCH * HID];

__device__ __forceinline__ u64 fma2(u64 a, u64 b, u64 c) {
    u64 d;
    asm("fma.rn.f32x2 %0, %1, %2, %3;" : "=l"(d) : "l"(a), "l"(b), "l"(c));
    return d;
}
__device__ __forceinline__ u64 add2(u64 a, u64 b) {
    u64 d;
    asm("add.rn.f32x2 %0, %1, %2;" : "=l"(d) : "l"(a), "l"(b));
    return d;
}
__device__ __forceinline__ float sum2(u64 a) {
    float lo, hi;
    asm("mov.b64 {%0, %1}, %2;" : "=f"(lo), "=f"(hi) : "l"(a));
    return lo + hi;
}

// ---------------------------------------------------------------------------
// Kernel 1: pre-pass v3.
// 296 CTAs x 256 threads (2 CTAs/SM), persistent over 8192 16-row blocks,
// double-buffered x staging. Inner loop processes ROW PAIRS: 4 independent
// accumulator chains + 2 independent LDS streams, fully unrolled.
// ---------------------------------------------------------------------------
#define PP_NCTA 296
#define PP_THR  256
#define PP_BLK_ROWS 16
#define PP_NBLK (T_STEPS * BATCH / PP_BLK_ROWS)     // 8192

__global__ void __launch_bounds__(PP_THR, 2)
ctrnn_prepass(const float* __restrict__ x,
              const float* __restrict__ noise,
              const float* __restrict__ Win,
              const float* __restrict__ bin,
              const float* __restrict__ bhh)
{
    __shared__ float xs[2][PP_BLK_ROWS * IN_SZ];    // 2 x 4 KB

    const int j = threadIdx.x;
    u64 w[IN_SZ / 2];
    #pragma unroll
    for (int m = 0; m < IN_SZ / 2; ++m)
        w[m] = *reinterpret_cast<const u64*>(&Win[j * IN_SZ + 2 * m]);
    const float bias = bin[j] + bhh[j];

    int blk = blockIdx.x;
    // prime buffer 0 (16 rows x 64 floats = 256 float4; thread j -> float4 #j)
    reinterpret_cast<float4*>(xs[0])[j] =
        reinterpret_cast<const float4*>(x + (size_t)blk * PP_BLK_ROWS * IN_SZ)[j];
    __syncthreads();
    int cur = 0;

    while (true) {
        const int nblk = blk + PP_NCTA;
        const bool has_next = nblk < PP_NBLK;

        // next block's x LDG issues early; hides under this block's compute
        float4 vn;
        if (has_next)
            vn = reinterpret_cast<const float4*>(
                     x + (size_t)nblk * PP_BLK_ROWS * IN_SZ)[j];

        // t constant within a 16-row block: hoist noise+bias
        const int   t  = blk >> 4;
        const float nb = noise[(size_t)t * HID + j] + bias;
        const size_t row0 = (size_t)blk * PP_BLK_ROWS;

        // ---- row-paired compute: 8 pairs, 4 chains each ----
        #pragma unroll 2
        for (int rp = 0; rp < PP_BLK_ROWS / 2; ++rp) {
            const ulonglong2* xrA =
                reinterpret_cast<const ulonglong2*>(&xs[cur][(2 * rp) * IN_SZ]);
            const ulonglong2* xrB =
                reinterpret_cast<const ulonglong2*>(&xs[cur][(2 * rp + 1) * IN_SZ]);
            u64 aA0 = 0, aA1 = 0, aB0 = 0, aB1 = 0;
            #pragma unroll
            for (int m = 0; m < IN_SZ / 4; ++m) {
                ulonglong2 xvA = xrA[m];
                ulonglong2 xvB = xrB[m];
                aA0 = fma2(w[2 * m],     xvA.x, aA0);
                aA1 = fma2(w[2 * m + 1], xvA.y, aA1);
                aB0 = fma2(w[2 * m],     xvB.x, aB0);
                aB1 = fma2(w[2 * m + 1], xvB.y, aB1);
            }
            g_pre[(row0 + 2 * rp)     * HID + j] = sum2(add2(aA0, aA1)) + nb;
            g_pre[(row0 + 2 * rp + 1) * HID + j] = sum2(add2(aB0, aB1)) + nb;
        }

        if (!has_next) break;
        // stage next block into the other buffer (safe with one bar/block:
        // reads of xs[cur^1] ended before the previous barrier).
        reinterpret_cast<float4*>(xs[cur ^ 1])[j] = vn;
        __syncthreads();
        cur ^= 1;
        blk = nblk;
    }
}

// ---------------------------------------------------------------------------
// Kernel 2: recurrent loop (aug K = 256, Whh only).
// Finalize spread: thread (g, jl) finalizes ONE item:
//   jl <  64 -> batch A, j = 64g + jl
//   jl >= 64 -> batch B, j = 64g + (jl-64)
// ---------------------------------------------------------------------------
__global__ void __launch_bounds__(NTHR, 1)
ctrnn_rec_kernel(const float* __restrict__ h0,
                 const float* __restrict__ Whh,
                 float* __restrict__ out,
                 float* __restrict__ hlast)
{
    extern __shared__ unsigned char smem_raw[];
    ulonglong2* Wsm = reinterpret_cast<ulonglong2*>(smem_raw);
    float* haug = reinterpret_cast<float*>(smem_raw + HAUG_OFF);  // [4][2][72]
    float* red  = reinterpret_cast<float*>(smem_raw + RED_OFF);   // [2][2][4][256]

    const int tid = threadIdx.x;
    const int g   = tid >> 7;          // k-group 0..3
    const int jl  = tid & 127;
    const int j0  = jl;
    const int j1  = jl + 128;
    const int b0  = blockIdx.x * 2;
    const int b1  = b0 + 1;

    // ---- stage W smem: chunk i covers Whh cols 64g+4i..+3, rows j0/j1 ----
    for (int i = 0; i < CHUNKS_PER_G; ++i) {
        const int col = ROWS_PER_G * g + 4 * i;
        *reinterpret_cast<float4*>(&Wsm[(g * CHUNKS_PER_G + i) * HID + j0]) =
            *reinterpret_cast<const float4*>(&Whh[j0 * HID + col]);
        *reinterpret_cast<float4*>(&Wsm[(g * CHUNKS_PER_G + i) * HID + j1]) =
            *reinterpret_cast<const float4*>(&Whh[j1 * HID + col]);
    }

    // ---- register W rows: Whh cols 64g+32 .. 64g+63 (16 u64 per j) ----
    u64 wr0[RF_U64], wr1[RF_U64];
    #pragma unroll
    for (int m = 0; m < RF_U64; ++m) {
        const int col = ROWS_PER_G * g + SMEM_ROWS_G + 2 * m;
        wr0[m] = *reinterpret_cast<const u64*>(&Whh[j0 * HID + col]);
        wr1[m] = *reinterpret_cast<const u64*>(&Whh[j1 * HID + col]);
    }

    // ---- finalize identity: one (batch, j) item per thread ----
    const int  fb   = jl >> 6;                 // 0 = batch A, 1 = batch B
    const int  fr   = jl & 63;                 // local row in slice
    const int  fj   = ROWS_PER_G * g + fr;     // global j
    const int  fbat = fb ? b1 : b0;

    float* myA = haug + (g * 2 + 0) * HAUG_STRIDE;
    float* myB = haug + (g * 2 + 1) * HAUG_STRIDE;
    float* fbuf = fb ? myB : myA;              // slice this thread finalizes into

    // ---- initial h staging (each thread stages its finalize item) ----
    fbuf[fr] = h0[fbat * HID + fj];
    __syncthreads();

    const ulonglong2* wp0 = Wsm + (size_t)(g * CHUNKS_PER_G) * HID + j0;
    const ulonglong2* wp1 = Wsm + (size_t)(g * CHUNKS_PER_G) * HID + j1;

    // ---- prime depth-1 W lookahead (chunk 0) ----
    ulonglong2 wb0 = wp0[0];
    ulonglong2 wb1 = wp1[0];

    for (int t = 0; t < T_STEPS; ++t) {
        float* redp = red + (t & 1) * RED_PAR_FLOATS;

        // prefetch this step's static pre-activation for my finalize item
        const float pre_v = g_pre[((size_t)t * BATCH + fbat) * HID + fj];

        // ---- interleaved FMA phase: (c r) x 8 slots ----
        u64 aA0 = 0, aA1 = 0, aB0 = 0, aB1 = 0;
        int ci = 0, ri = 0;

        #pragma unroll
        for (int k = 0; k < NSLOTS; ++k) {
            if (k & 1) {
                // RF slot ri: local rows 32+4*ri
                ulonglong2 ha = *reinterpret_cast<const ulonglong2*>(&myA[SMEM_ROWS_G + 4 * ri]);
                ulonglong2 hb = *reinterpret_cast<const ulonglong2*>(&myB[SMEM_ROWS_G + 4 * ri]);
                aA0 = fma2(wr0[2 * ri], ha.x, aA0);  aA0 = fma2(wr0[2 * ri + 1], ha.y, aA0);
                aA1 = fma2(wr1[2 * ri], ha.x, aA1);  aA1 = fma2(wr1[2 * ri + 1], ha.y, aA1);
                aB0 = fma2(wr0[2 * ri], hb.x, aB0);  aB0 = fma2(wr0[2 * ri + 1], hb.y, aB0);
                aB1 = fma2(wr1[2 * ri], hb.x, aB1);  aB1 = fma2(wr1[2 * ri + 1], hb.y, aB1);
                ++ri;
            } else {
                // chunk slot ci: consume buffered W, issue chunk (ci+1)%8;
                // last chunk slot fetches NEXT step's chunk 0 pre-barrier.
                const ulonglong2 w0 = wb0;
                const ulonglong2 w1 = wb1;
                int nc = ci + 1;
                if (nc >= CHUNKS_PER_G) nc = 0;
                wb0 = wp0[(size_t)nc * HID];
                wb1 = wp1[(size_t)nc * HID];

                ulonglong2 ha = *reinterpret_cast<const ulonglong2*>(&myA[4 * ci]);
                ulonglong2 hb = *reinterpret_cast<const ulonglong2*>(&myB[4 * ci]);
                aA0 = fma2(w0.x, ha.x, aA0);  aA0 = fma2(w0.y, ha.y, aA0);
                aA1 = fma2(w1.x, ha.x, aA1);  aA1 = fma2(w1.y, ha.y, aA1);
                aB0 = fma2(w0.x, hb.x, aB0);  aB0 = fma2(w0.y, hb.y, aB0);
                aB1 = fma2(w1.x, hb.x, aB1);  aB1 = fma2(w1.y, hb.y, aB1);
                ++ci;
            }
        }

        redp[(0 * NGROUP + g) * HID + j0] = sum2(aA0);
        redp[(0 * NGROUP + g) * HID + j1] = sum2(aA1);
        redp[(1 * NGROUP + g) * HID + j0] = sum2(aB0);
        redp[(1 * NGROUP + g) * HID + j1] = sum2(aB1);
        __syncthreads();                       // the ONE full-CTA barrier

        // ---- finalize my single (batch, j) item ----
        {
            const float* rb = redp + fb * NGROUP * HID;
            const float s = rb[0 * HID + fj] + rb[1 * HID + fj]
                          + rb[2 * HID + fj] + rb[3 * HID + fj];
            const float hn = fmaxf(fbuf[fr] * 0.8f + (s + pre_v) * 0.2f, 0.f);
            if (out) out[((size_t)t * BATCH + fbat) * HID + fj] = hn;
            fbuf[fr] = hn;
        }

        asm volatile("bar.sync %0, %1;" :: "r"(g + 1), "r"(128) : "memory");
    }

    if (hlast)
        hlast[fbat * HID + fj] = fbuf[fr];
}

extern "C" void kernel_launch(void* const* d_in, const int* in_sizes, int n_in,
                              void* d_out, int out_size)
{
    const float* x     = (const float*)d_in[0];   // [512,256,64]
    const float* h0    = (const float*)d_in[1];   // [256,256]
    const float* noise = (const float*)d_in[2];   // [512,256]
    const float* Win   = (const float*)d_in[3];   // [256,64]
    const float* bin   = (const float*)d_in[4];   // [256]
    const float* Whh   = (const float*)d_in[5];   // [256,256]
    const float* bhh   = (const float*)d_in[6];   // [256]

    const size_t TBH = (size_t)T_STEPS * BATCH * HID;
    const size_t BH  = (size_t)BATCH * HID;

    float* out   = nullptr;
    float* hlast = nullptr;
    if ((size_t)out_size >= TBH) {
        out = (float*)d_out;
        if ((size_t)out_size >= TBH + BH) hlast = (float*)d_out + TBH;
    } else {
        hlast = (float*)d_out;
    }

    static bool attr_set = false;
    if (!attr_set) {
        cudaFuncSetAttribute(ctrnn_rec_kernel,
                             cudaFuncAttributeMaxDynamicSharedMemorySize, SMEM_TOTAL);
        attr_set = true;
    }

    ctrnn_prepass<<<PP_NCTA, PP_THR>>>(x, noise, Win, bin, bhh);
    ctrnn_rec_kernel<<<NCTA, NTHR, SMEM_TOTAL>>>(h0, Whh, out, hlast);
}